// round 16
// baseline (speedup 1.0000x reference)
#include <cuda_runtime.h>
#include <cuda_fp16.h>
#include <cstddef>
#include <cstdint>

#define BB 64
#define NN 2048
#define II 16
#define JJ 32
#define OO 32
#define JO 1024      // J*O
#define NB 8         // n's per stage/round in pass_kernel (== #warps)
#define CHUNK 128    // n's per pass CTA (16 chunks)
#define NROUND 16    // CHUNK / NB
#define STAGE_BYTES (NB * JO * 2)   // 16 KB
#define PASS_DYN_SMEM (4 * STAGE_BYTES + 4096 + 1024)   // 70656 B
#define NCH0 32      // sum0 chunks
#define CH0 64       // n's per sum0 CTA
#define S0_STAGE (8 * 128 * 16)     // 16 KB
#define S0_DYN_SMEM (4 * S0_STAGE)  // 64 KB

// Scratch (allocation-free rule: __device__ globals).
__device__ __half g_predh[(size_t)BB * NN * JO];        // 256 MB fp16 predictions
__device__ float g_pA[(size_t)NCH0 * BB * JO];          // partial buffer A (8 MB)
__device__ float g_pB[(size_t)16 * BB * JO];            // partial buffer B (4 MB)
__device__ float g_v[BB * JO];                          // squashed v
__device__ float g_blog[(size_t)BB * NN * JJ];          // routing logits (pass1 -> pass2)

__device__ __forceinline__ float4 h4_to_f4(uint2 u) {
    __half2 h0 = *reinterpret_cast<__half2*>(&u.x);
    __half2 h1 = *reinterpret_cast<__half2*>(&u.y);
    float2 a = __half22float2(h0);
    float2 c = __half22float2(h1);
    return make_float4(a.x, a.y, c.x, c.y);
}

// ---------------------------------------------------------------------------
// K1: predictions via HFMA2 (R15 version — at its memory floor; unchanged).
// One CTA per n, 256 threads; thread t owns jo [4t,4t+4).
// ---------------------------------------------------------------------------
__global__ __launch_bounds__(256, 2)
void pred_kernel(const float* __restrict__ x, const float* __restrict__ w) {
    const int n = blockIdx.x;
    const int t = threadIdx.x;

    __shared__ __half2 xs[BB][II];   // (x,x) fp16 pairs, 4 KB
    {
        int b = t >> 2, q = t & 3;
        float4 f = reinterpret_cast<const float4*>(x + ((size_t)b * NN + n) * II)[q];
        xs[b][4 * q + 0] = __float2half2_rn(f.x);
        xs[b][4 * q + 1] = __float2half2_rn(f.y);
        xs[b][4 * q + 2] = __float2half2_rn(f.z);
        xs[b][4 * q + 3] = __float2half2_rn(f.w);
    }

    __half2 wh01[16], wh23[16];
    {
        const float4* wp = reinterpret_cast<const float4*>(
            w + ((size_t)n * JO + 4 * t) * II);
#pragma unroll
        for (int c = 0; c < 4; ++c) {
            float4 r0 = wp[c];
            float4 r1 = wp[4 + c];
            wh01[4 * c + 0] = __floats2half2_rn(r0.x, r1.x);
            wh01[4 * c + 1] = __floats2half2_rn(r0.y, r1.y);
            wh01[4 * c + 2] = __floats2half2_rn(r0.z, r1.z);
            wh01[4 * c + 3] = __floats2half2_rn(r0.w, r1.w);
        }
#pragma unroll
        for (int c = 0; c < 4; ++c) {
            float4 r2 = wp[8 + c];
            float4 r3 = wp[12 + c];
            wh23[4 * c + 0] = __floats2half2_rn(r2.x, r3.x);
            wh23[4 * c + 1] = __floats2half2_rn(r2.y, r3.y);
            wh23[4 * c + 2] = __floats2half2_rn(r2.z, r3.z);
            wh23[4 * c + 3] = __floats2half2_rn(r2.w, r3.w);
        }
    }
    __syncthreads();

    __half* outp = g_predh + (size_t)n * JO + 4 * t;

#pragma unroll 4
    for (int b = 0; b < BB; ++b) {
        __half2 xx[16];
        {
            const uint4* xp = reinterpret_cast<const uint4*>(&xs[b][0]);
#pragma unroll
            for (int q = 0; q < 4; ++q) {
                uint4 u = xp[q];
                xx[4 * q + 0] = *reinterpret_cast<__half2*>(&u.x);
                xx[4 * q + 1] = *reinterpret_cast<__half2*>(&u.y);
                xx[4 * q + 2] = *reinterpret_cast<__half2*>(&u.z);
                xx[4 * q + 3] = *reinterpret_cast<__half2*>(&u.w);
            }
        }
        __half2 z = __float2half2_rn(0.f);
        __half2 a01a = z, a01b = z, a23a = z, a23b = z;
#pragma unroll
        for (int i = 0; i < 8; ++i) {
            a01a = __hfma2(xx[i], wh01[i], a01a);
            a23a = __hfma2(xx[i], wh23[i], a23a);
            a01b = __hfma2(xx[i + 8], wh01[i + 8], a01b);
            a23b = __hfma2(xx[i + 8], wh23[i + 8], a23b);
        }
        __half2 h01 = __hadd2(a01a, a01b);
        __half2 h23 = __hadd2(a23a, a23b);
        uint2 st;
        st.x = *reinterpret_cast<unsigned int*>(&h01);
        st.y = *reinterpret_cast<unsigned int*>(&h23);
        *reinterpret_cast<uint2*>(outp + (size_t)b * NN * JO) = st;
    }
}

// ---------------------------------------------------------------------------
// K2: iter-0 s partials. Barrier-free per-thread pipeline, now 4-stage with
// depth-3 prefetch (3 stages = 48 KB in flight during consumption; dynamic
// smem 64 KB -> 3 CTAs/SM -> 144 KB in flight per SM).
// ---------------------------------------------------------------------------
__global__ __launch_bounds__(128)
void sum0_kernel() {
    extern __shared__ __align__(16) unsigned char s0dyn[];
    const int chunk = blockIdx.x;   // 0..31
    const int b = blockIdx.y;
    const int t = threadIdx.x;      // octet index 0..127

    const char* gsrc = reinterpret_cast<const char*>(
        g_predh + ((size_t)b * NN + (size_t)chunk * CH0) * JO);
    const uint32_t sb0 = (uint32_t)__cvta_generic_to_shared(s0dyn);

    auto issue = [&](int s) {
        const char* g = gsrc + (size_t)s * S0_STAGE;
        uint32_t d = sb0 + (s & 3) * S0_STAGE;
#pragma unroll
        for (int k = 0; k < 8; ++k) {
            uint32_t off = (k * 128 + t) * 16;
            asm volatile("cp.async.cg.shared.global [%0], [%1], 16;"
                         :: "r"(d + off), "l"(g + off));
        }
        asm volatile("cp.async.commit_group;");
    };

    issue(0); issue(1); issue(2);
    float sacc[8];
#pragma unroll
    for (int e = 0; e < 8; ++e) sacc[e] = 0.f;

    for (int s = 0; s < 8; ++s) {
        if (s + 3 < 8) { issue(s + 3); asm volatile("cp.async.wait_group 3;"); }
        else if (s + 2 < 8) { asm volatile("cp.async.wait_group 2;"); }
        else if (s + 1 < 8) { asm volatile("cp.async.wait_group 1;"); }
        else { asm volatile("cp.async.wait_group 0;"); }

        const unsigned char* sp = s0dyn + (s & 3) * S0_STAGE;
#pragma unroll
        for (int k = 0; k < 8; ++k) {
            uint4 r = *reinterpret_cast<const uint4*>(sp + (k * 128 + t) * 16);
            float2 f0 = __half22float2(*reinterpret_cast<__half2*>(&r.x));
            float2 f1 = __half22float2(*reinterpret_cast<__half2*>(&r.y));
            float2 f2 = __half22float2(*reinterpret_cast<__half2*>(&r.z));
            float2 f3 = __half22float2(*reinterpret_cast<__half2*>(&r.w));
            sacc[0] += f0.x; sacc[1] += f0.y; sacc[2] += f1.x; sacc[3] += f1.y;
            sacc[4] += f2.x; sacc[5] += f2.y; sacc[6] += f3.x; sacc[7] += f3.y;
        }
    }
    const float inv = 1.0f / 32.0f;
    float* dst = g_pA + ((size_t)chunk * BB + b) * JO + t * 8;
    reinterpret_cast<float4*>(dst)[0] =
        make_float4(sacc[0] * inv, sacc[1] * inv, sacc[2] * inv, sacc[3] * inv);
    reinterpret_cast<float4*>(dst)[1] =
        make_float4(sacc[4] * inv, sacc[5] * inv, sacc[6] * inv, sacc[7] * inv);
}

// ---------------------------------------------------------------------------
// K3: reduce partials + squash -> g_v (and optionally d_out).
// ---------------------------------------------------------------------------
template <int NCHIN, bool INA>
__global__ __launch_bounds__(1024)
void v_kernel(float* __restrict__ out) {
    const float* pin = INA ? g_pA : g_pB;
    const int b = blockIdx.x;
    const int t = threadIdx.x;
    float s = 0.f;
#pragma unroll
    for (int k = 0; k < NCHIN; ++k)
        s += pin[((size_t)k * BB + b) * JO + t];
    float sq = s * s;
#pragma unroll
    for (int m = 16; m > 0; m >>= 1)
        sq += __shfl_xor_sync(0xffffffffu, sq, m);
    float scale = (sq / (1.0f + sq)) * rsqrtf(sq + 1e-8f);
    float v = s * scale;
    g_v[b * JO + t] = v;
    if (out) out[b * JO + t] = v;
}

// ---------------------------------------------------------------------------
// K4: routing pass (iters 1,2). 4-stage cp.async ring, depth-3 prefetch
// (3 stages / 48 KB in flight during consumption), end-of-round barrier
// REMOVED: issue(r+3) targets slot (r-1)%4, and every warp past round r's
// post-wait barrier has finished phase C of round r-1, so the slot is free.
// 3 barriers/round. 69 KB dyn smem -> 3 CTAs/SM -> 144 KB in flight.
//   MODE 1: a = pred.v,  blog = a, softmax(a)
//   MODE 2: a = blog + pred.v,    softmax(a)
// ---------------------------------------------------------------------------
template <int MODE, bool OUTA>
__global__ __launch_bounds__(256)
void pass_kernel() {
    extern __shared__ __align__(16) unsigned char dyn[];
    float (*a_part)[JJ][4] = reinterpret_cast<float(*)[JJ][4]>(dyn + 4 * STAGE_BYTES);
    float (*c_buf)[JJ] = reinterpret_cast<float(*)[JJ]>(dyn + 4 * STAGE_BYTES + 4096);

    const int chunk = blockIdx.x;
    const int b = blockIdx.y;
    const int t = threadIdx.x;
    const int warp = t >> 5;
    const int lane = t & 31;
    const int j = t >> 3;
    const int sub = t & 7;

    const float4 vv = reinterpret_cast<const float4*>(g_v + b * JO)[t];
    float4 sacc = make_float4(0.f, 0.f, 0.f, 0.f);

    const char* gsrc = reinterpret_cast<const char*>(
        g_predh + ((size_t)b * NN + (size_t)chunk * CHUNK) * JO);
    const uint32_t sb0 = (uint32_t)__cvta_generic_to_shared(dyn);

    auto issue = [&](int r) {
        const char* g = gsrc + (size_t)r * STAGE_BYTES;
        uint32_t d = sb0 + (r & 3) * STAGE_BYTES;
#pragma unroll
        for (int i = 0; i < 4; ++i) {
            uint32_t off = (i * 256 + t) * 16;
            asm volatile("cp.async.cg.shared.global [%0], [%1], 16;"
                         :: "r"(d + off), "l"(g + off));
        }
        asm volatile("cp.async.commit_group;");
    };

    issue(0); issue(1); issue(2);

    for (int r = 0; r < NROUND; ++r) {
        if (r + 3 < NROUND) { issue(r + 3); asm volatile("cp.async.wait_group 3;"); }
        else if (r + 2 < NROUND) { asm volatile("cp.async.wait_group 2;"); }
        else if (r + 1 < NROUND) { asm volatile("cp.async.wait_group 1;"); }
        else { asm volatile("cp.async.wait_group 0;"); }
        __syncthreads();   // stage r visible to all threads

        const uint32_t sb = sb0 + (r & 3) * STAGE_BYTES;

        // phase A: partial dots, one pre-reduce shuffle, half-lanes write
#pragma unroll
        for (int k = 0; k < NB; ++k) {
            uint2 u;
            asm("ld.shared.v2.u32 {%0, %1}, [%2];"
                : "=r"(u.x), "=r"(u.y) : "r"(sb + k * (JO * 2) + t * 8));
            float4 p = h4_to_f4(u);
            float d = p.x * vv.x + p.y * vv.y + p.z * vv.z + p.w * vv.w;
            d += __shfl_xor_sync(0xffffffffu, d, 4);
            if (sub < 4) a_part[k][j][sub] = d;
        }
        __syncthreads();

        {   // phase B: warp k finishes dot for n = base+k, blog, softmax
            const int k = warp;
            const int n = chunk * CHUNK + r * NB + k;
            float4 q = *reinterpret_cast<const float4*>(&a_part[k][lane][0]);
            float a = (q.x + q.y) + (q.z + q.w);
            size_t bidx = ((size_t)b * NN + n) * JJ + lane;
            if (MODE == 2) a += g_blog[bidx];
            else           g_blog[bidx] = a;     // b1 = agreement (b0 = 0)
            float m = a;
#pragma unroll
            for (int s = 16; s > 0; s >>= 1)
                m = fmaxf(m, __shfl_xor_sync(0xffffffffu, m, s));
            float e = __expf(a - m);
            float ssum = e;
#pragma unroll
            for (int s = 16; s > 0; s >>= 1)
                ssum += __shfl_xor_sync(0xffffffffu, ssum, s);
            c_buf[k][lane] = e / ssum;
        }
        __syncthreads();

        // phase C: c-weighted accumulation (re-read pred from smem)
#pragma unroll
        for (int k = 0; k < NB; ++k) {
            float c = c_buf[k][j];
            uint2 u;
            asm("ld.shared.v2.u32 {%0, %1}, [%2];"
                : "=r"(u.x), "=r"(u.y) : "r"(sb + k * (JO * 2) + t * 8));
            float4 p = h4_to_f4(u);
            sacc.x = fmaf(c, p.x, sacc.x);
            sacc.y = fmaf(c, p.y, sacc.y);
            sacc.z = fmaf(c, p.z, sacc.z);
            sacc.w = fmaf(c, p.w, sacc.w);
        }
        // no end-of-round barrier: next round's issue targets slot (r-1)%4,
        // already drained by the post-wait barrier above.
    }

    float* pout = OUTA ? g_pA : g_pB;
    reinterpret_cast<float4*>(pout + ((size_t)chunk * BB + b) * JO)[t] = sacc;
}

// ---------------------------------------------------------------------------
extern "C" void kernel_launch(void* const* d_in, const int* in_sizes, int n_in,
                              void* d_out, int out_size) {
    const float* x = (const float*)d_in[0];   // [64, 2048, 16] f32
    const float* w = (const float*)d_in[1];   // [2048, 32, 32, 16] f32
    float* out = (float*)d_out;               // [64, 32, 32] f32

    cudaFuncSetAttribute(sum0_kernel,
                         cudaFuncAttributeMaxDynamicSharedMemorySize, S0_DYN_SMEM);
    cudaFuncSetAttribute(pass_kernel<1, false>,
                         cudaFuncAttributeMaxDynamicSharedMemorySize, PASS_DYN_SMEM);
    cudaFuncSetAttribute(pass_kernel<2, true>,
                         cudaFuncAttributeMaxDynamicSharedMemorySize, PASS_DYN_SMEM);

    pred_kernel<<<NN, 256>>>(x, w);
    sum0_kernel<<<dim3(NCH0, BB), 128, S0_DYN_SMEM>>>();         // s0 -> A (32)
    v_kernel<NCH0, true><<<BB, 1024>>>(nullptr);                 // v0
    pass_kernel<1, false><<<dim3(16, BB), 256, PASS_DYN_SMEM>>>();  // s1 -> B
    v_kernel<16, false><<<BB, 1024>>>(nullptr);                  // v1
    pass_kernel<2, true><<<dim3(16, BB), 256, PASS_DYN_SMEM>>>();   // s2 -> A
    v_kernel<16, true><<<BB, 1024>>>(out);                       // v2 -> output
}

// round 17
// speedup vs baseline: 1.0949x; 1.0949x over previous
#include <cuda_runtime.h>
#include <cuda_fp16.h>
#include <cstddef>
#include <cstdint>

#define BB 64
#define NN 2048
#define II 16
#define JJ 32
#define OO 32
#define JO 1024      // J*O
#define NB 8         // n's per stage/round in pass_kernel (== #warps)
#define CHUNK 128    // n's per pass CTA (16 chunks)
#define NROUND 16    // CHUNK / NB
#define STAGE_BYTES (NB * JO * 2)   // 16 KB
#define PASS_DYN_SMEM (3 * STAGE_BYTES + 4096 + 1024)   // 53.25 KB -> 4 CTAs/SM
#define NCH0 32      // sum0 chunks
#define CH0 64       // n's per sum0 CTA
#define S0_STAGE (8 * 128 * 16)     // 16 KB

// Scratch (allocation-free rule: __device__ globals).
__device__ __half g_predh[(size_t)BB * NN * JO];        // 256 MB fp16 predictions
__device__ float g_pA[(size_t)NCH0 * BB * JO];          // partial buffer A (8 MB)
__device__ float g_pB[(size_t)16 * BB * JO];            // partial buffer B (4 MB)
__device__ float g_v[BB * JO];                          // squashed v
__device__ float g_blog[(size_t)BB * NN * JJ];          // routing logits (pass1 -> pass2)

__device__ __forceinline__ float4 h4_to_f4(uint2 u) {
    __half2 h0 = *reinterpret_cast<__half2*>(&u.x);
    __half2 h1 = *reinterpret_cast<__half2*>(&u.y);
    float2 a = __half22float2(h0);
    float2 c = __half22float2(h1);
    return make_float4(a.x, a.y, c.x, c.y);
}

// ---------------------------------------------------------------------------
// K1: predictions via HFMA2. R17: 128 threads/CTA, thread owns a jo-OCTET
// [8t, 8t+8) -> one STG.128 per b instead of two STG.64 across two threads
// (25% less LSU issue, half the loop-control instructions). Same HFMA2 total
// and same rounding sequence as R15 (two 8-chains + HADD2 per jo-pair) ->
// bit-identical output.
// ---------------------------------------------------------------------------
__global__ __launch_bounds__(128, 4)
void pred_kernel(const float* __restrict__ x, const float* __restrict__ w) {
    const int n = blockIdx.x;
    const int t = threadIdx.x;   // 0..127, owns jo [8t, 8t+8)

    __shared__ __half2 xs[BB][II];   // (x,x) fp16 pairs, 4 KB
#pragma unroll
    for (int idx = t; idx < 256; idx += 128) {
        int b = idx >> 2, q = idx & 3;
        float4 f = reinterpret_cast<const float4*>(x + ((size_t)b * NN + n) * II)[q];
        xs[b][4 * q + 0] = __float2half2_rn(f.x);
        xs[b][4 * q + 1] = __float2half2_rn(f.y);
        xs[b][4 * q + 2] = __float2half2_rn(f.z);
        xs[b][4 * q + 3] = __float2half2_rn(f.w);
    }

    // pack w: 4 jo-pairs x 16 i, row-pair at a time (no fp32 staging array)
    __half2 wh[4][16];
    {
        const float4* wp = reinterpret_cast<const float4*>(
            w + ((size_t)n * JO + 8 * t) * II);
#pragma unroll
        for (int p = 0; p < 4; ++p) {
#pragma unroll
            for (int c = 0; c < 4; ++c) {
                float4 r0 = wp[(2 * p) * 4 + c];      // row jo 2p
                float4 r1 = wp[(2 * p + 1) * 4 + c];  // row jo 2p+1
                wh[p][4 * c + 0] = __floats2half2_rn(r0.x, r1.x);
                wh[p][4 * c + 1] = __floats2half2_rn(r0.y, r1.y);
                wh[p][4 * c + 2] = __floats2half2_rn(r0.z, r1.z);
                wh[p][4 * c + 3] = __floats2half2_rn(r0.w, r1.w);
            }
        }
    }
    __syncthreads();

    __half* outp = g_predh + (size_t)n * JO + 8 * t;

#pragma unroll 2
    for (int b = 0; b < BB; ++b) {
        // 16 (x,x) pairs via 4 broadcast LDS.128
        __half2 xx[16];
        {
            const uint4* xp = reinterpret_cast<const uint4*>(&xs[b][0]);
#pragma unroll
            for (int q = 0; q < 4; ++q) {
                uint4 u = xp[q];
                xx[4 * q + 0] = *reinterpret_cast<__half2*>(&u.x);
                xx[4 * q + 1] = *reinterpret_cast<__half2*>(&u.y);
                xx[4 * q + 2] = *reinterpret_cast<__half2*>(&u.z);
                xx[4 * q + 3] = *reinterpret_cast<__half2*>(&u.w);
            }
        }
        const __half2 z = __float2half2_rn(0.f);
        uint4 st;
        unsigned int* stw = reinterpret_cast<unsigned int*>(&st);
#pragma unroll
        for (int p = 0; p < 4; ++p) {
            __half2 aa = z, ab = z;
#pragma unroll
            for (int i = 0; i < 8; ++i) {
                aa = __hfma2(xx[i], wh[p][i], aa);
                ab = __hfma2(xx[i + 8], wh[p][i + 8], ab);
            }
            __half2 h = __hadd2(aa, ab);
            stw[p] = *reinterpret_cast<unsigned int*>(&h);
        }
        *reinterpret_cast<uint4*>(outp + (size_t)b * NN * JO) = st;
    }
}

// ---------------------------------------------------------------------------
// K2: iter-0 s partials. Barrier-free per-thread 3-stage cp.async pipeline
// (R10/R15 champion config). 128 threads; thread t owns jo octet [8t, 8t+8).
// ---------------------------------------------------------------------------
__global__ __launch_bounds__(128)
void sum0_kernel() {
    __shared__ __align__(16) unsigned char st[3][S0_STAGE];   // 48 KB
    const int chunk = blockIdx.x;   // 0..31
    const int b = blockIdx.y;
    const int t = threadIdx.x;      // octet index 0..127

    const char* gsrc = reinterpret_cast<const char*>(
        g_predh + ((size_t)b * NN + (size_t)chunk * CH0) * JO);
    const uint32_t sb0 = (uint32_t)__cvta_generic_to_shared(&st[0][0]);

    auto issue = [&](int s) {
        const char* g = gsrc + (size_t)s * S0_STAGE;
        uint32_t d = sb0 + (s % 3) * S0_STAGE;
#pragma unroll
        for (int k = 0; k < 8; ++k) {
            uint32_t off = (k * 128 + t) * 16;
            asm volatile("cp.async.cg.shared.global [%0], [%1], 16;"
                         :: "r"(d + off), "l"(g + off));
        }
        asm volatile("cp.async.commit_group;");
    };

    issue(0); issue(1);
    float sacc[8];
#pragma unroll
    for (int e = 0; e < 8; ++e) sacc[e] = 0.f;

    for (int s = 0; s < 8; ++s) {
        if (s + 2 < 8) { issue(s + 2); asm volatile("cp.async.wait_group 2;"); }
        else if (s + 1 < 8) { asm volatile("cp.async.wait_group 1;"); }
        else { asm volatile("cp.async.wait_group 0;"); }

        const unsigned char* sp = &st[s % 3][0];
#pragma unroll
        for (int k = 0; k < 8; ++k) {
            uint4 r = *reinterpret_cast<const uint4*>(sp + (k * 128 + t) * 16);
            float2 f0 = __half22float2(*reinterpret_cast<__half2*>(&r.x));
            float2 f1 = __half22float2(*reinterpret_cast<__half2*>(&r.y));
            float2 f2 = __half22float2(*reinterpret_cast<__half2*>(&r.z));
            float2 f3 = __half22float2(*reinterpret_cast<__half2*>(&r.w));
            sacc[0] += f0.x; sacc[1] += f0.y; sacc[2] += f1.x; sacc[3] += f1.y;
            sacc[4] += f2.x; sacc[5] += f2.y; sacc[6] += f3.x; sacc[7] += f3.y;
        }
    }
    const float inv = 1.0f / 32.0f;
    float* dst = g_pA + ((size_t)chunk * BB + b) * JO + t * 8;
    reinterpret_cast<float4*>(dst)[0] =
        make_float4(sacc[0] * inv, sacc[1] * inv, sacc[2] * inv, sacc[3] * inv);
    reinterpret_cast<float4*>(dst)[1] =
        make_float4(sacc[4] * inv, sacc[5] * inv, sacc[6] * inv, sacc[7] * inv);
}

// ---------------------------------------------------------------------------
// K3: reduce partials + squash -> g_v (and optionally d_out).
// ---------------------------------------------------------------------------
template <int NCHIN, bool INA>
__global__ __launch_bounds__(1024)
void v_kernel(float* __restrict__ out) {
    const float* pin = INA ? g_pA : g_pB;
    const int b = blockIdx.x;
    const int t = threadIdx.x;
    float s = 0.f;
#pragma unroll
    for (int k = 0; k < NCHIN; ++k)
        s += pin[((size_t)k * BB + b) * JO + t];
    float sq = s * s;
#pragma unroll
    for (int m = 16; m > 0; m >>= 1)
        sq += __shfl_xor_sync(0xffffffffu, sq, m);
    float scale = (sq / (1.0f + sq)) * rsqrtf(sq + 1e-8f);
    float v = s * scale;
    g_v[b * JO + t] = v;
    if (out) out[b * JO + t] = v;
}

// ---------------------------------------------------------------------------
// K4: routing pass (iters 1,2) with 3-stage cp.async ring (R10/R15 champion).
// ---------------------------------------------------------------------------
template <int MODE, bool OUTA>
__global__ __launch_bounds__(256)
void pass_kernel() {
    extern __shared__ __align__(16) unsigned char dyn[];
    float (*a_part)[JJ][4] = reinterpret_cast<float(*)[JJ][4]>(dyn + 3 * STAGE_BYTES);
    float (*c_buf)[JJ] = reinterpret_cast<float(*)[JJ]>(dyn + 3 * STAGE_BYTES + 4096);

    const int chunk = blockIdx.x;
    const int b = blockIdx.y;
    const int t = threadIdx.x;
    const int warp = t >> 5;
    const int lane = t & 31;
    const int j = t >> 3;
    const int sub = t & 7;

    const float4 vv = reinterpret_cast<const float4*>(g_v + b * JO)[t];
    float4 sacc = make_float4(0.f, 0.f, 0.f, 0.f);

    const char* gsrc = reinterpret_cast<const char*>(
        g_predh + ((size_t)b * NN + (size_t)chunk * CHUNK) * JO);
    const uint32_t sb0 = (uint32_t)__cvta_generic_to_shared(dyn);

    auto issue = [&](int r) {
        const char* g = gsrc + (size_t)r * STAGE_BYTES;
        uint32_t d = sb0 + (r % 3) * STAGE_BYTES;
#pragma unroll
        for (int i = 0; i < 4; ++i) {
            uint32_t off = (i * 256 + t) * 16;
            asm volatile("cp.async.cg.shared.global [%0], [%1], 16;"
                         :: "r"(d + off), "l"(g + off));
        }
        asm volatile("cp.async.commit_group;");
    };

    issue(0); issue(1);

    for (int r = 0; r < NROUND; ++r) {
        if (r + 2 < NROUND) { issue(r + 2); asm volatile("cp.async.wait_group 2;"); }
        else if (r + 1 < NROUND) { asm volatile("cp.async.wait_group 1;"); }
        else { asm volatile("cp.async.wait_group 0;"); }
        __syncthreads();

        const uint32_t sb = sb0 + (r % 3) * STAGE_BYTES;

#pragma unroll
        for (int k = 0; k < NB; ++k) {
            uint2 u;
            asm("ld.shared.v2.u32 {%0, %1}, [%2];"
                : "=r"(u.x), "=r"(u.y) : "r"(sb + k * (JO * 2) + t * 8));
            float4 p = h4_to_f4(u);
            float d = p.x * vv.x + p.y * vv.y + p.z * vv.z + p.w * vv.w;
            d += __shfl_xor_sync(0xffffffffu, d, 4);
            if (sub < 4) a_part[k][j][sub] = d;
        }
        __syncthreads();

        {
            const int k = warp;
            const int n = chunk * CHUNK + r * NB + k;
            float4 q = *reinterpret_cast<const float4*>(&a_part[k][lane][0]);
            float a = (q.x + q.y) + (q.z + q.w);
            size_t bidx = ((size_t)b * NN + n) * JJ + lane;
            if (MODE == 2) a += g_blog[bidx];
            else           g_blog[bidx] = a;
            float m = a;
#pragma unroll
            for (int s = 16; s > 0; s >>= 1)
                m = fmaxf(m, __shfl_xor_sync(0xffffffffu, m, s));
            float e = __expf(a - m);
            float ssum = e;
#pragma unroll
            for (int s = 16; s > 0; s >>= 1)
                ssum += __shfl_xor_sync(0xffffffffu, ssum, s);
            c_buf[k][lane] = e / ssum;
        }
        __syncthreads();

#pragma unroll
        for (int k = 0; k < NB; ++k) {
            float c = c_buf[k][j];
            uint2 u;
            asm("ld.shared.v2.u32 {%0, %1}, [%2];"
                : "=r"(u.x), "=r"(u.y) : "r"(sb + k * (JO * 2) + t * 8));
            float4 p = h4_to_f4(u);
            sacc.x = fmaf(c, p.x, sacc.x);
            sacc.y = fmaf(c, p.y, sacc.y);
            sacc.z = fmaf(c, p.z, sacc.z);
            sacc.w = fmaf(c, p.w, sacc.w);
        }
        __syncthreads();
    }

    float* pout = OUTA ? g_pA : g_pB;
    reinterpret_cast<float4*>(pout + ((size_t)chunk * BB + b) * JO)[t] = sacc;
}

// ---------------------------------------------------------------------------
extern "C" void kernel_launch(void* const* d_in, const int* in_sizes, int n_in,
                              void* d_out, int out_size) {
    const float* x = (const float*)d_in[0];   // [64, 2048, 16] f32
    const float* w = (const float*)d_in[1];   // [2048, 32, 32, 16] f32
    float* out = (float*)d_out;               // [64, 32, 32] f32

    cudaFuncSetAttribute(pass_kernel<1, false>,
                         cudaFuncAttributeMaxDynamicSharedMemorySize, PASS_DYN_SMEM);
    cudaFuncSetAttribute(pass_kernel<2, true>,
                         cudaFuncAttributeMaxDynamicSharedMemorySize, PASS_DYN_SMEM);

    pred_kernel<<<NN, 128>>>(x, w);
    sum0_kernel<<<dim3(NCH0, BB), 128>>>();                      // s0 -> A (32)
    v_kernel<NCH0, true><<<BB, 1024>>>(nullptr);                 // v0
    pass_kernel<1, false><<<dim3(16, BB), 256, PASS_DYN_SMEM>>>();  // s1 -> B
    v_kernel<16, false><<<BB, 1024>>>(nullptr);                  // v1
    pass_kernel<2, true><<<dim3(16, BB), 256, PASS_DYN_SMEM>>>();   // s2 -> A
    v_kernel<16, true><<<BB, 1024>>>(out);                       // v2 -> output
}